// round 12
// baseline (speedup 1.0000x reference)
#include <cuda_runtime.h>
#include <cuda_fp16.h>
#include <math.h>

// Problem constants (fixed shapes per reference)
#define NN   100000
#define EE   3200000
#define HIGH 384
#define LOW  64
#define EMB  128
#define HID  128

#define SCAN_B 1024
#define NB_SCAN ((NN + SCAN_B - 1) / SCAN_B)   // 98

// ---------------- scratch (device globals; no allocation allowed) -------------
__device__ __align__(16) int   g_counts[NN];
__device__ __align__(16) int   g_rowptr[NN + 1];
__device__ __align__(16) int   g_cursor[NN];
__device__ __align__(16) int   g_blockSums[128];
__device__ __align__(16) int   g_blockOff[128];
__device__ __align__(16) float g_dis[NN];
__device__ __align__(16) int2  g_edge[EE];                   // (src, w bits)
__device__ __align__(16) __half g_embH[(size_t)NN * 128];    // fp16 embedding
__device__ __align__(16) __half g_xl[(size_t)NN * 128];      // fp16 pre-agg features
__device__ __align__(16) __half g_x1H[(size_t)NN * 128];     // fp16 layer-1 output
// fp16 n-major transposed weights: W1T[128][512], W2T[128][128], WembT[128][64]
__device__ __align__(16) __half g_wT[128 * 512 + 128 * 128 + 128 * 64];
#define W1T_OFF   0
#define W2T_OFF   (128 * 512)
#define WEMBT_OFF (128 * 512 + 128 * 128)

// ---------------- weight transpose+convert: W[K][128] -> WT[128][K] fp16 ------
__global__ void k_wT(const float* __restrict__ W, __half* __restrict__ WT, int K) {
    int idx = blockIdx.x * 256 + threadIdx.x;
    if (idx < K * 128) {
        int k = idx >> 7;
        int n = idx & 127;
        WT[n * K + k] = __float2half_rn(W[k * 128 + n]);
    }
}

// ---------------- degree count ----------------
__global__ void k_count(const int* __restrict__ dst) {
    int e = blockIdx.x * blockDim.x + threadIdx.x;
    if (e < EE) atomicAdd(&g_counts[dst[e]], 1);
}

// ---------------- exclusive scan of counts -> rowptr (+dis) ----------------
__global__ void k_scan1() {
    __shared__ int s[SCAN_B];
    int tid = threadIdx.x;
    int idx = blockIdx.x * SCAN_B + tid;
    int v = (idx < NN) ? g_counts[idx] : 0;
    if (idx < NN) g_dis[idx] = rsqrtf((float)v + 1.0f);
    s[tid] = v;
    __syncthreads();
    for (int off = 1; off < SCAN_B; off <<= 1) {
        int t = (tid >= off) ? s[tid - off] : 0;
        __syncthreads();
        s[tid] += t;
        __syncthreads();
    }
    if (idx < NN) g_rowptr[idx] = s[tid] - v;      // partial exclusive
    if (tid == SCAN_B - 1) g_blockSums[blockIdx.x] = s[tid];
}

__global__ void k_scan2() {
    __shared__ int s[128];
    int tid = threadIdx.x;
    int v = (tid < NB_SCAN) ? g_blockSums[tid] : 0;
    s[tid] = v;
    __syncthreads();
    for (int off = 1; off < 128; off <<= 1) {
        int t = (tid >= off) ? s[tid - off] : 0;
        __syncthreads();
        s[tid] += t;
        __syncthreads();
    }
    if (tid < NB_SCAN) g_blockOff[tid] = s[tid] - v;
    if (tid == 127) g_rowptr[NN] = s[127];         // == EE
}

__global__ void k_scan3() {
    int tid = threadIdx.x;
    int idx = blockIdx.x * SCAN_B + tid;
    if (idx < NN) {
        int r = g_rowptr[idx] + g_blockOff[blockIdx.x];
        g_rowptr[idx] = r;
        g_cursor[idx] = r;
    }
}

// ---------------- scatter edges into CSR (by dst) ----------------
__global__ void k_scatter(const int* __restrict__ src, const int* __restrict__ dst) {
    int e = blockIdx.x * blockDim.x + threadIdx.x;
    if (e < EE) {
        int d = dst[e];
        int s = src[e];
        int p = atomicAdd(&g_cursor[d], 1);
        g_edge[p] = make_int2(s, __float_as_int(g_dis[s]));
    }
}

// ---------------- cp.async helpers ----------------
__device__ __forceinline__ void cp16(void* smem, const void* gmem) {
    unsigned sa = (unsigned)__cvta_generic_to_shared(smem);
    asm volatile("cp.async.cg.shared.global [%0], [%1], 16;" :: "r"(sa), "l"(gmem));
}
__device__ __forceinline__ void cp_commit() {
    asm volatile("cp.async.commit_group;");
}
__device__ __forceinline__ void cp_wait0() {
    asm volatile("cp.async.wait_group 0;" ::: "memory");
}

// ---------------- ldmatrix helper ----------------
__device__ __forceinline__ void ldsm_x4(unsigned& r0, unsigned& r1,
                                        unsigned& r2, unsigned& r3, unsigned addr) {
    asm volatile("ldmatrix.sync.aligned.m8n8.x4.shared.b16 {%0,%1,%2,%3}, [%4];"
        : "=r"(r0), "=r"(r1), "=r"(r2), "=r"(r3) : "r"(addr));
}

// ---------------- fp16 tensor-core GEMM, async double-buffered ----------------
// C_h[M,128] = [Af | Ah] @ W  (+bias, +relu), output fp16.
// Af: fp32 A part (row stride Ka); Ah: fp16 A part (row stride Kh).
// WT: fp16 n-major weights [128][Ka+Kh].
// BM=128, BN=128, BK=32; 256 threads = 8 warps as 2(m) x 4(n); warp tile 64x32.
// Fragments via ldmatrix.x4 (bank-conflict-free on 80B row stride).

__device__ __forceinline__ void mma_f16(float* d, const unsigned* a, const unsigned* b) {
    asm volatile(
        "mma.sync.aligned.m16n8k16.row.col.f32.f16.f16.f32 "
        "{%0,%1,%2,%3}, {%4,%5,%6,%7}, {%8,%9}, {%0,%1,%2,%3};"
        : "+f"(d[0]), "+f"(d[1]), "+f"(d[2]), "+f"(d[3])
        : "r"(a[0]), "r"(a[1]), "r"(a[2]), "r"(a[3]), "r"(b[0]), "r"(b[1]));
}

#define APAD 40   // halves per SMEM row (32 data + 8 pad); 80 bytes

__global__ void __launch_bounds__(256, 2)
k_mma(const float* __restrict__ Af, int Ka,
      const __half* __restrict__ Ah, int Kh,
      const __half* __restrict__ WT, __half* __restrict__ C, int M,
      const float* __restrict__ bias, int doRelu) {
    __shared__ __half As[2][128][APAD];
    __shared__ __half Ws[2][128][APAD];

    int tid  = threadIdx.x;
    int row0 = blockIdx.x * 128;
    int warpId = tid >> 5;
    int lane   = tid & 31;
    int g   = lane >> 2;       // groupID (0..7)
    int tig = lane & 3;        // thread-in-group (0..3)
    int wr = warpId >> 2;      // 0..1  -> m offset wr*64
    int wc = warpId & 3;       // 0..3  -> n offset wc*32
    int m0 = wr * 64;
    int n0 = wc * 32;
    int K  = Ka + Kh;
    int nk = K >> 5;           // k-chunks of 32
    int nka = Ka >> 5;         // fp32 chunks

    // ldmatrix per-lane address offsets
    int lrow = lane & 7;
    int lsel = lane >> 3;                 // 0..3
    int a_row_off = (lsel & 1) * 8 + lrow; // A: matrices 0/1 = row 0/8, 2/3 = k+8
    int a_k_off   = (lsel >> 1) * 8;       // halves
    int b_row_off = (lsel >> 1) * 8 + lrow;// B: matrices 0/1 = k 0/8, 2/3 = n+8
    int b_k_off   = (lsel & 1) * 8;

    float acc[4][4][4];        // [mf][nf][c0..c3]
    #pragma unroll
    for (int i = 0; i < 4; i++)
        #pragma unroll
        for (int j = 0; j < 4; j++)
            #pragma unroll
            for (int c = 0; c < 4; c++) acc[i][j][c] = 0.0f;

    // fp32 A prefetch registers (4 float4 per thread)
    float4 rA[4];

    // ---- issue tile kc into buffer b / regs ----
    auto issue = [&](int kc, int b) {
        int k0 = kc << 5;
        if (kc < nka) {
            // fp32 A -> regs (convert at STS)
            #pragma unroll
            for (int i = 0; i < 4; i++) {
                int l   = tid + i * 256;
                int row = l >> 3;
                int c4  = (l & 7) * 4;
                int grow = row0 + row;
                float4 v = make_float4(0.f, 0.f, 0.f, 0.f);
                if (grow < M) v = *(const float4*)(Af + (size_t)grow * Ka + k0 + c4);
                rA[i] = v;
            }
        } else {
            // fp16 A -> cp.async
            int kh0 = k0 - Ka;
            #pragma unroll
            for (int i = 0; i < 2; i++) {
                int q   = tid + i * 256;
                int row = q >> 2;
                int c8  = (q & 3) * 8;
                int gr  = row0 + row; if (gr > M - 1) gr = M - 1;
                cp16(&As[b][row][c8], Ah + (size_t)gr * Kh + kh0 + c8);
            }
        }
        // W -> cp.async (WT row stride = K halves)
        #pragma unroll
        for (int i = 0; i < 2; i++) {
            int q  = tid + i * 256;
            int n  = q >> 2;
            int c8 = (q & 3) * 8;
            cp16(&Ws[b][n][c8], WT + (size_t)n * K + k0 + c8);
        }
        cp_commit();
    };

    issue(0, 0);

    for (int kc = 0; kc < nk; kc++) {
        int kb = kc & 1;
        if (kc < nka) {
            // STS prefetched fp32 A (convert now)
            #pragma unroll
            for (int i = 0; i < 4; i++) {
                int l   = tid + i * 256;
                int row = l >> 3;
                int c4  = (l & 7) * 4;
                *(__half2*)&As[kb][row][c4 + 0] = __floats2half2_rn(rA[i].x, rA[i].y);
                *(__half2*)&As[kb][row][c4 + 2] = __floats2half2_rn(rA[i].z, rA[i].w);
            }
        }
        cp_wait0();
        __syncthreads();

        if (kc + 1 < nk) issue(kc + 1, kb ^ 1);

        unsigned aBase = (unsigned)__cvta_generic_to_shared(&As[kb][0][0]);
        unsigned wBase = (unsigned)__cvta_generic_to_shared(&Ws[kb][0][0]);

        #pragma unroll
        for (int ks = 0; ks < 2; ks++) {   // two k16 steps
            int kh = ks * 16;
            unsigned af[4][4];
            #pragma unroll
            for (int mf = 0; mf < 4; mf++) {
                unsigned ad = aBase +
                    ((unsigned)(m0 + mf * 16 + a_row_off) * APAD + kh + a_k_off) * 2u;
                ldsm_x4(af[mf][0], af[mf][1], af[mf][2], af[mf][3], ad);
            }
            unsigned bf[4][2];
            #pragma unroll
            for (int nfp = 0; nfp < 2; nfp++) {
                unsigned bd = wBase +
                    ((unsigned)(n0 + nfp * 16 + b_row_off) * APAD + kh + b_k_off) * 2u;
                ldsm_x4(bf[2 * nfp][0], bf[2 * nfp][1],
                        bf[2 * nfp + 1][0], bf[2 * nfp + 1][1], bd);
            }
            #pragma unroll
            for (int mf = 0; mf < 4; mf++)
                #pragma unroll
                for (int nf = 0; nf < 4; nf++)
                    mma_f16(acc[mf][nf], af[mf], bf[nf]);
        }
        __syncthreads();
    }

    // --- epilogue (fp16 out) ---
    #pragma unroll
    for (int mf = 0; mf < 4; mf++) {
        int ra = row0 + m0 + mf * 16 + g;     // row for c0,c1
        int rb = ra + 8;                      // row for c2,c3
        #pragma unroll
        for (int nf = 0; nf < 4; nf++) {
            int col = n0 + nf * 8 + 2 * tig;
            float b0 = bias ? bias[col]     : 0.0f;
            float b1 = bias ? bias[col + 1] : 0.0f;
            #pragma unroll
            for (int h = 0; h < 2; h++) {
                int r = h ? rb : ra;
                if (r >= M) continue;
                float2 o = make_float2(acc[mf][nf][2 * h]     + b0,
                                       acc[mf][nf][2 * h + 1] + b1);
                if (doRelu) { o.x = fmaxf(o.x, 0.f); o.y = fmaxf(o.y, 0.f); }
                *(__half2*)(C + (size_t)r * 128 + col) = __float22half2_rn(o);
            }
        }
    }
}

// ---------------- packed f32x2 helpers (sm_100) ----------------
__device__ __forceinline__ unsigned long long pk2(float x, float y) {
    unsigned long long r;
    asm("mov.b64 %0, {%1, %2};" : "=l"(r) : "f"(x), "f"(y));
    return r;
}
__device__ __forceinline__ void fma2(unsigned long long& d,
                                     unsigned long long a, unsigned long long b) {
    asm("fma.rn.f32x2 %0, %1, %2, %0;" : "+l"(d) : "l"(a), "l"(b));
}
__device__ __forceinline__ float2 up2(unsigned long long v) {
    float2 f;
    asm("mov.b64 {%0, %1}, %2;" : "=f"(f.x), "=f"(f.y) : "l"(v));
    return f;
}

// ---------------- GCN aggregation core (fp16 gathers), one warp per node ------
// 4 independent gather streams; packed fma.rn.f32x2 accumulation (fp32 pairs).
__device__ __forceinline__ float4 agg_node(int i, int lane, const float* bias) {
    float di = g_dis[i];
    const uint2* xb = (const uint2*)g_xl;     // index: node*32 + lane
    uint2 sr = __ldg(xb + (size_t)i * 32 + lane);
    float2 selfLo = __half22float2(*(__half2*)&sr.x);
    float2 selfHi = __half22float2(*(__half2*)&sr.y);

    int beg = g_rowptr[i];
    int end = g_rowptr[i + 1];

    unsigned long long aLo[4], aHi[4];
    #pragma unroll
    for (int j = 0; j < 4; j++) { aLo[j] = pk2(0.f, 0.f); aHi[j] = pk2(0.f, 0.f); }

    int e = beg;
    for (; e + 4 <= end; e += 4) {
        int2 E[4];
        #pragma unroll
        for (int j = 0; j < 4; j++) E[j] = g_edge[e + j];
        uint2 R[4];
        #pragma unroll
        for (int j = 0; j < 4; j++) R[j] = __ldg(xb + (size_t)E[j].x * 32 + lane);
        #pragma unroll
        for (int j = 0; j < 4; j++) {
            float w = __int_as_float(E[j].y);
            unsigned long long w2 = pk2(w, w);
            float2 lo = __half22float2(*(__half2*)&R[j].x);
            float2 hi = __half22float2(*(__half2*)&R[j].y);
            fma2(aLo[j], pk2(lo.x, lo.y), w2);
            fma2(aHi[j], pk2(hi.x, hi.y), w2);
        }
    }
    for (; e < end; e++) {
        int2 ed = g_edge[e];
        uint2 rr = __ldg(xb + (size_t)ed.x * 32 + lane);
        float w = __int_as_float(ed.y);
        unsigned long long w2 = pk2(w, w);
        float2 lo = __half22float2(*(__half2*)&rr.x);
        float2 hi = __half22float2(*(__half2*)&rr.y);
        fma2(aLo[0], pk2(lo.x, lo.y), w2);
        fma2(aHi[0], pk2(hi.x, hi.y), w2);
    }

    float2 l0 = up2(aLo[0]), l1 = up2(aLo[1]), l2 = up2(aLo[2]), l3 = up2(aLo[3]);
    float2 h0 = up2(aHi[0]), h1 = up2(aHi[1]), h2 = up2(aHi[2]), h3 = up2(aHi[3]);
    float4 nsum;
    nsum.x = (l0.x + l1.x) + (l2.x + l3.x);
    nsum.y = (l0.y + l1.y) + (l2.y + l3.y);
    nsum.z = (h0.x + h1.x) + (h2.x + h3.x);
    nsum.w = (h0.y + h1.y) + (h2.y + h3.y);

    float4 bv = *((const float4*)bias + lane);
    float dii = di * di;
    float4 r;
    r.x = fmaxf(di * nsum.x + dii * selfLo.x + bv.x, 0.f);
    r.y = fmaxf(di * nsum.y + dii * selfLo.y + bv.y, 0.f);
    r.z = fmaxf(di * nsum.z + dii * selfHi.x + bv.z, 0.f);
    r.w = fmaxf(di * nsum.w + dii * selfHi.y + bv.w, 0.f);
    return r;
}

// agg -> fp16 output (feeds next GEMM)
__global__ void __launch_bounds__(256)
k_gcn_agg_h(const float* __restrict__ bias, __half* __restrict__ out) {
    int warp = (blockIdx.x * blockDim.x + threadIdx.x) >> 5;
    int lane = threadIdx.x & 31;
    if (warp >= NN) return;
    float4 r = agg_node(warp, lane, bias);
    __half2 h01 = __floats2half2_rn(r.x, r.y);
    __half2 h23 = __floats2half2_rn(r.z, r.w);
    uint2 o;
    o.x = *(unsigned*)&h01;
    o.y = *(unsigned*)&h23;
    *((uint2*)out + (size_t)warp * 32 + lane) = o;
}

// agg + head (x@W_lin + b_lin, log_softmax) fused
__global__ void __launch_bounds__(256)
k_agg_head(const float* __restrict__ bias, const float* __restrict__ Wl,
           const float* __restrict__ bl, float* __restrict__ out) {
    int warp = (blockIdx.x * blockDim.x + threadIdx.x) >> 5;
    int lane = threadIdx.x & 31;
    if (warp >= NN) return;
    float4 x = agg_node(warp, lane, bias);

    int c0 = lane * 4;
    float4 w01 = *(const float4*)(Wl + c0 * 2);      // rows c0, c0+1
    float4 w23 = *(const float4*)(Wl + c0 * 2 + 4);  // rows c0+2, c0+3
    float a0 = x.x * w01.x + x.y * w01.z + x.z * w23.x + x.w * w23.z;
    float a1 = x.x * w01.y + x.y * w01.w + x.z * w23.y + x.w * w23.w;
    #pragma unroll
    for (int o = 16; o > 0; o >>= 1) {
        a0 += __shfl_down_sync(0xffffffffu, a0, o);
        a1 += __shfl_down_sync(0xffffffffu, a1, o);
    }
    if (lane == 0) {
        float z0 = a0 + bl[0];
        float z1 = a1 + bl[1];
        float m  = fmaxf(z0, z1);
        float lse = m + logf(expf(z0 - m) + expf(z1 - m));
        out[(size_t)warp * 2 + 0] = z0 - lse;
        out[(size_t)warp * 2 + 1] = z1 - lse;
    }
}

// -----------------------------------------------------------------------------
extern "C" void kernel_launch(void* const* d_in, const int* in_sizes, int n_in,
                              void* d_out, int out_size) {
    const float* high  = (const float*)d_in[0];
    const float* low   = (const float*)d_in[1];
    const int*   eidx  = (const int*)d_in[2];
    const float* W_emb = (const float*)d_in[3];
    const float* b_emb = (const float*)d_in[4];
    const float* W1    = (const float*)d_in[5];
    const float* b1    = (const float*)d_in[6];
    const float* W2    = (const float*)d_in[7];
    const float* b2    = (const float*)d_in[8];
    const float* W_lin = (const float*)d_in[9];
    const float* b_lin = (const float*)d_in[10];
    float* out = (float*)d_out;

    const int* src = eidx;        // edge_index[0]
    const int* dst = eidx + EE;   // edge_index[1]

    int*    countsP; cudaGetSymbolAddress((void**)&countsP, g_counts);
    __half* embH;    cudaGetSymbolAddress((void**)&embH,    g_embH);
    __half* xlH;     cudaGetSymbolAddress((void**)&xlH,     g_xl);
    __half* x1H;     cudaGetSymbolAddress((void**)&x1H,     g_x1H);
    __half* wT;      cudaGetSymbolAddress((void**)&wT,      g_wT);

    const int T = 256;
    dim3 gE((EE + T - 1) / T);
    dim3 gWarpN((NN * 32 + T - 1) / T);
    dim3 gGemm((NN + 127) / 128);

    cudaMemsetAsync(countsP, 0, NN * sizeof(int));

    // 1-2: weight transposes needed by the first two GEMMs
    k_wT<<<(LOW * 128 + 255) / 256, 256>>>(W_emb, wT + WEMBT_OFF, LOW);          // 1
    k_wT<<<(512 * 128 + 255) / 256, 256>>>(W1, wT + W1T_OFF, 512);               // 2

    // 3: embedding: embH = relu(low @ W_emb + b_emb)  (fp16)
    k_mma<<<gGemm, 256>>>(low, LOW, (const __half*)nullptr, 0,                   // 3
                          wT + WEMBT_OFF, embH, NN, b_emb, 1);

    // 4: layer 1 (fused K=512): xl = [high | embH] @ W1 -> fp16   [ncu slot]
    k_mma<<<gGemm, 256>>>(high, HIGH, embH, EMB,                                 // 4
                          wT + W1T_OFF, xlH, NN, nullptr, 0);

    // CSR chain (independent of GEMMs; after, to keep layer-1 at slot 4)
    k_count<<<gE, T>>>(dst);                                                     // 5
    k_scan1<<<NB_SCAN, SCAN_B>>>();                                              // 6
    k_wT<<<(HID * 128 + 255) / 256, 256>>>(W2, wT + W2T_OFF, HID);               // 7
    k_scan2<<<1, 128>>>();                                                       // 8
    k_scan3<<<NB_SCAN, SCAN_B>>>();                                              // 9
    k_scatter<<<gE, T>>>(src, dst);                                              // 10

    // x1 = relu(agg(xl) + b1) -> fp16
    k_gcn_agg_h<<<gWarpN, T>>>(b1, x1H);                                         // 11

    // layer 2: xl = x1 @ W2 -> fp16
    k_mma<<<gGemm, 256>>>((const float*)nullptr, 0, x1H, HID,                    // 12
                          wT + W2T_OFF, xlH, NN, nullptr, 0);

    // agg2 + head + log_softmax (fused)
    k_agg_head<<<gWarpN, T>>>(b2, W_lin, b_lin, out);                            // 13
}

// round 14
// speedup vs baseline: 1.0300x; 1.0300x over previous
#include <cuda_runtime.h>
#include <cuda_fp16.h>
#include <math.h>

// Problem constants (fixed shapes per reference)
#define NN   100000
#define EE   3200000
#define HIGH 384
#define LOW  64
#define EMB  128
#define HID  128

#define SCAN_B 1024
#define NB_SCAN ((NN + SCAN_B - 1) / SCAN_B)   // 98

// ---------------- scratch (device globals; no allocation allowed) -------------
__device__ __align__(16) int   g_counts[NN];
__device__ __align__(16) int   g_rowptr[NN + 1];
__device__ __align__(16) int   g_cursor[NN];
__device__ __align__(16) int   g_blockSums[128];
__device__ __align__(16) int   g_blockOff[128];
__device__ __align__(16) float g_dis[NN];
__device__ __align__(16) int2  g_edge[EE];                   // (src, w bits)
__device__ __align__(16) __half g_embH[(size_t)NN * 128];    // fp16 embedding
__device__ __align__(16) __half g_xl[(size_t)NN * 128];      // fp16 pre-agg features
__device__ __align__(16) __half g_x1H[(size_t)NN * 128];     // fp16 layer-1 output
// fp16 n-major transposed weights: W1T[128][512], W2T[128][128], WembT[128][64]
__device__ __align__(16) __half g_wT[128 * 512 + 128 * 128 + 128 * 64];
#define W1T_OFF   0
#define W2T_OFF   (128 * 512)
#define WEMBT_OFF (128 * 512 + 128 * 128)

// ---------------- weight transpose+convert: W[K][128] -> WT[128][K] fp16 ------
__global__ void k_wT(const float* __restrict__ W, __half* __restrict__ WT, int K) {
    int idx = blockIdx.x * 256 + threadIdx.x;
    if (idx < K * 128) {
        int k = idx >> 7;
        int n = idx & 127;
        WT[n * K + k] = __float2half_rn(W[k * 128 + n]);
    }
}

// ---------------- degree count ----------------
__global__ void k_count(const int* __restrict__ dst) {
    int e = blockIdx.x * blockDim.x + threadIdx.x;
    if (e < EE) atomicAdd(&g_counts[dst[e]], 1);
}

// ---------------- exclusive scan of counts -> rowptr (+dis) ----------------
__global__ void k_scan1() {
    __shared__ int s[SCAN_B];
    int tid = threadIdx.x;
    int idx = blockIdx.x * SCAN_B + tid;
    int v = (idx < NN) ? g_counts[idx] : 0;
    if (idx < NN) g_dis[idx] = rsqrtf((float)v + 1.0f);
    s[tid] = v;
    __syncthreads();
    for (int off = 1; off < SCAN_B; off <<= 1) {
        int t = (tid >= off) ? s[tid - off] : 0;
        __syncthreads();
        s[tid] += t;
        __syncthreads();
    }
    if (idx < NN) g_rowptr[idx] = s[tid] - v;      // partial exclusive
    if (tid == SCAN_B - 1) g_blockSums[blockIdx.x] = s[tid];
}

__global__ void k_scan2() {
    __shared__ int s[128];
    int tid = threadIdx.x;
    int v = (tid < NB_SCAN) ? g_blockSums[tid] : 0;
    s[tid] = v;
    __syncthreads();
    for (int off = 1; off < 128; off <<= 1) {
        int t = (tid >= off) ? s[tid - off] : 0;
        __syncthreads();
        s[tid] += t;
        __syncthreads();
    }
    if (tid < NB_SCAN) g_blockOff[tid] = s[tid] - v;
    if (tid == 127) g_rowptr[NN] = s[127];         // == EE
}

__global__ void k_scan3() {
    int tid = threadIdx.x;
    int idx = blockIdx.x * SCAN_B + tid;
    if (idx < NN) {
        int r = g_rowptr[idx] + g_blockOff[blockIdx.x];
        g_rowptr[idx] = r;
        g_cursor[idx] = r;
    }
}

// ---------------- scatter edges into CSR (by dst) ----------------
__global__ void k_scatter(const int* __restrict__ src, const int* __restrict__ dst) {
    int e = blockIdx.x * blockDim.x + threadIdx.x;
    if (e < EE) {
        int d = dst[e];
        int s = src[e];
        int p = atomicAdd(&g_cursor[d], 1);
        g_edge[p] = make_int2(s, __float_as_int(g_dis[s]));
    }
}

// ---------------- cp.async helpers ----------------
__device__ __forceinline__ void cp16(void* smem, const void* gmem) {
    unsigned sa = (unsigned)__cvta_generic_to_shared(smem);
    asm volatile("cp.async.cg.shared.global [%0], [%1], 16;" :: "r"(sa), "l"(gmem));
}
__device__ __forceinline__ void cp_commit() {
    asm volatile("cp.async.commit_group;");
}
__device__ __forceinline__ void cp_wait0() {
    asm volatile("cp.async.wait_group 0;" ::: "memory");
}

// ---------------- ldmatrix helper ----------------
__device__ __forceinline__ void ldsm_x4(unsigned& r0, unsigned& r1,
                                        unsigned& r2, unsigned& r3, unsigned addr) {
    asm volatile("ldmatrix.sync.aligned.m8n8.x4.shared.b16 {%0,%1,%2,%3}, [%4];"
        : "=r"(r0), "=r"(r1), "=r"(r2), "=r"(r3) : "r"(addr));
}

// ---------------- fp16 tensor-core GEMM, async double-buffered ----------------
// C_h[M,128] = [Af | Ah] @ W  (+bias, +relu), output fp16.
// Af: fp32 A part (row stride Ka); Ah: fp16 A part (row stride Kh).
// WT: fp16 n-major weights [128][Ka+Kh].
// BM=128, BN=128, BK=32; 256 threads = 8 warps as 2(m) x 4(n); warp tile 64x32.
// Fragments via ldmatrix.x4 (bank-conflict-free on 80B row stride).

__device__ __forceinline__ void mma_f16(float* d, const unsigned* a, const unsigned* b) {
    asm volatile(
        "mma.sync.aligned.m16n8k16.row.col.f32.f16.f16.f32 "
        "{%0,%1,%2,%3}, {%4,%5,%6,%7}, {%8,%9}, {%0,%1,%2,%3};"
        : "+f"(d[0]), "+f"(d[1]), "+f"(d[2]), "+f"(d[3])
        : "r"(a[0]), "r"(a[1]), "r"(a[2]), "r"(a[3]), "r"(b[0]), "r"(b[1]));
}

#define APAD 40   // halves per SMEM row (32 data + 8 pad); 80 bytes

__global__ void __launch_bounds__(256, 2)
k_mma(const float* __restrict__ Af, int Ka,
      const __half* __restrict__ Ah, int Kh,
      const __half* __restrict__ WT, __half* __restrict__ C, int M,
      const float* __restrict__ bias, int doRelu) {
    __shared__ __half As[2][128][APAD];
    __shared__ __half Ws[2][128][APAD];

    int tid  = threadIdx.x;
    int row0 = blockIdx.x * 128;
    int warpId = tid >> 5;
    int lane   = tid & 31;
    int g   = lane >> 2;       // groupID (0..7)
    int tig = lane & 3;        // thread-in-group (0..3)
    int wr = warpId >> 2;      // 0..1  -> m offset wr*64
    int wc = warpId & 3;       // 0..3  -> n offset wc*32
    int m0 = wr * 64;
    int n0 = wc * 32;
    int K  = Ka + Kh;
    int nk = K >> 5;           // k-chunks of 32
    int nka = Ka >> 5;         // fp32 chunks

    // ldmatrix per-lane address offsets
    int lrow = lane & 7;
    int lsel = lane >> 3;                 // 0..3
    int a_row_off = (lsel & 1) * 8 + lrow; // A: matrices 0/1 = row 0/8, 2/3 = k+8
    int a_k_off   = (lsel >> 1) * 8;       // halves
    int b_row_off = (lsel >> 1) * 8 + lrow;// B: matrices 0/1 = k 0/8, 2/3 = n+8
    int b_k_off   = (lsel & 1) * 8;

    float acc[4][4][4];        // [mf][nf][c0..c3]
    #pragma unroll
    for (int i = 0; i < 4; i++)
        #pragma unroll
        for (int j = 0; j < 4; j++)
            #pragma unroll
            for (int c = 0; c < 4; c++) acc[i][j][c] = 0.0f;

    // fp32 A prefetch registers (4 float4 per thread)
    float4 rA[4];

    // ---- issue tile kc into buffer b / regs ----
    auto issue = [&](int kc, int b) {
        int k0 = kc << 5;
        if (kc < nka) {
            // fp32 A -> regs (convert at STS)
            #pragma unroll
            for (int i = 0; i < 4; i++) {
                int l   = tid + i * 256;
                int row = l >> 3;
                int c4  = (l & 7) * 4;
                int grow = row0 + row;
                float4 v = make_float4(0.f, 0.f, 0.f, 0.f);
                if (grow < M) v = *(const float4*)(Af + (size_t)grow * Ka + k0 + c4);
                rA[i] = v;
            }
        } else {
            // fp16 A -> cp.async
            int kh0 = k0 - Ka;
            #pragma unroll
            for (int i = 0; i < 2; i++) {
                int q   = tid + i * 256;
                int row = q >> 2;
                int c8  = (q & 3) * 8;
                int gr  = row0 + row; if (gr > M - 1) gr = M - 1;
                cp16(&As[b][row][c8], Ah + (size_t)gr * Kh + kh0 + c8);
            }
        }
        // W -> cp.async (WT row stride = K halves)
        #pragma unroll
        for (int i = 0; i < 2; i++) {
            int q  = tid + i * 256;
            int n  = q >> 2;
            int c8 = (q & 3) * 8;
            cp16(&Ws[b][n][c8], WT + (size_t)n * K + k0 + c8);
        }
        cp_commit();
    };

    issue(0, 0);

    for (int kc = 0; kc < nk; kc++) {
        int kb = kc & 1;
        if (kc < nka) {
            // STS prefetched fp32 A (convert now)
            #pragma unroll
            for (int i = 0; i < 4; i++) {
                int l   = tid + i * 256;
                int row = l >> 3;
                int c4  = (l & 7) * 4;
                *(__half2*)&As[kb][row][c4 + 0] = __floats2half2_rn(rA[i].x, rA[i].y);
                *(__half2*)&As[kb][row][c4 + 2] = __floats2half2_rn(rA[i].z, rA[i].w);
            }
        }
        cp_wait0();
        __syncthreads();

        if (kc + 1 < nk) issue(kc + 1, kb ^ 1);

        unsigned aBase = (unsigned)__cvta_generic_to_shared(&As[kb][0][0]);
        unsigned wBase = (unsigned)__cvta_generic_to_shared(&Ws[kb][0][0]);

        #pragma unroll
        for (int ks = 0; ks < 2; ks++) {   // two k16 steps
            int kh = ks * 16;
            unsigned af[4][4];
            #pragma unroll
            for (int mf = 0; mf < 4; mf++) {
                unsigned ad = aBase +
                    ((unsigned)(m0 + mf * 16 + a_row_off) * APAD + kh + a_k_off) * 2u;
                ldsm_x4(af[mf][0], af[mf][1], af[mf][2], af[mf][3], ad);
            }
            unsigned bf[4][2];
            #pragma unroll
            for (int nfp = 0; nfp < 2; nfp++) {
                unsigned bd = wBase +
                    ((unsigned)(n0 + nfp * 16 + b_row_off) * APAD + kh + b_k_off) * 2u;
                ldsm_x4(bf[2 * nfp][0], bf[2 * nfp][1],
                        bf[2 * nfp + 1][0], bf[2 * nfp + 1][1], bd);
            }
            #pragma unroll
            for (int mf = 0; mf < 4; mf++)
                #pragma unroll
                for (int nf = 0; nf < 4; nf++)
                    mma_f16(acc[mf][nf], af[mf], bf[nf]);
        }
        __syncthreads();
    }

    // --- epilogue (fp16 out) ---
    #pragma unroll
    for (int mf = 0; mf < 4; mf++) {
        int ra = row0 + m0 + mf * 16 + g;     // row for c0,c1
        int rb = ra + 8;                      // row for c2,c3
        #pragma unroll
        for (int nf = 0; nf < 4; nf++) {
            int col = n0 + nf * 8 + 2 * tig;
            float b0 = bias ? bias[col]     : 0.0f;
            float b1 = bias ? bias[col + 1] : 0.0f;
            #pragma unroll
            for (int h = 0; h < 2; h++) {
                int r = h ? rb : ra;
                if (r >= M) continue;
                float2 o = make_float2(acc[mf][nf][2 * h]     + b0,
                                       acc[mf][nf][2 * h + 1] + b1);
                if (doRelu) { o.x = fmaxf(o.x, 0.f); o.y = fmaxf(o.y, 0.f); }
                *(__half2*)(C + (size_t)r * 128 + col) = __float22half2_rn(o);
            }
        }
    }
}

// ---------------- GCN aggregation core (fp16 gathers), one warp per node ------
// 4 independent gather streams per warp, plain fp32 fmaf accumulate
// (R10-measured best configuration; packed f32x2 variant regressed).
__device__ __forceinline__ float4 agg_node(int i, int lane, const float* bias) {
    float di = g_dis[i];
    const uint2* xb = (const uint2*)g_xl;     // index: node*32 + lane
    uint2 sr = __ldg(xb + (size_t)i * 32 + lane);
    float2 selfLo = __half22float2(*(__half2*)&sr.x);
    float2 selfHi = __half22float2(*(__half2*)&sr.y);

    int beg = g_rowptr[i];
    int end = g_rowptr[i + 1];

    float4 s0 = make_float4(0.f, 0.f, 0.f, 0.f);
    float4 s1 = make_float4(0.f, 0.f, 0.f, 0.f);
    float4 s2 = make_float4(0.f, 0.f, 0.f, 0.f);
    float4 s3 = make_float4(0.f, 0.f, 0.f, 0.f);

    int e = beg;
    for (; e + 4 <= end; e += 4) {
        int2 e0 = g_edge[e + 0], e1 = g_edge[e + 1];
        int2 e2 = g_edge[e + 2], e3 = g_edge[e + 3];
        uint2 r0 = __ldg(xb + (size_t)e0.x * 32 + lane);
        uint2 r1 = __ldg(xb + (size_t)e1.x * 32 + lane);
        uint2 r2 = __ldg(xb + (size_t)e2.x * 32 + lane);
        uint2 r3 = __ldg(xb + (size_t)e3.x * 32 + lane);
        float w0 = __int_as_float(e0.y), w1 = __int_as_float(e1.y);
        float w2 = __int_as_float(e2.y), w3 = __int_as_float(e3.y);
        {
            float2 lo = __half22float2(*(__half2*)&r0.x);
            float2 hi = __half22float2(*(__half2*)&r0.y);
            s0.x = fmaf(w0, lo.x, s0.x); s0.y = fmaf(w0, lo.y, s0.y);
            s0.z = fmaf(w0, hi.x, s0.z); s0.w = fmaf(w0, hi.y, s0.w);
        }
        {
            float2 lo = __half22float2(*(__half2*)&r1.x);
            float2 hi = __half22float2(*(__half2*)&r1.y);
            s1.x = fmaf(w1, lo.x, s1.x); s1.y = fmaf(w1, lo.y, s1.y);
            s1.z = fmaf(w1, hi.x, s1.z); s1.w = fmaf(w1, hi.y, s1.w);
        }
        {
            float2 lo = __half22float2(*(__half2*)&r2.x);
            float2 hi = __half22float2(*(__half2*)&r2.y);
            s2.x = fmaf(w2, lo.x, s2.x); s2.y = fmaf(w2, lo.y, s2.y);
            s2.z = fmaf(w2, hi.x, s2.z); s2.w = fmaf(w2, hi.y, s2.w);
        }
        {
            float2 lo = __half22float2(*(__half2*)&r3.x);
            float2 hi = __half22float2(*(__half2*)&r3.y);
            s3.x = fmaf(w3, lo.x, s3.x); s3.y = fmaf(w3, lo.y, s3.y);
            s3.z = fmaf(w3, hi.x, s3.z); s3.w = fmaf(w3, hi.y, s3.w);
        }
    }
    for (; e < end; e++) {
        int2 ed = g_edge[e];
        uint2 rr = __ldg(xb + (size_t)ed.x * 32 + lane);
        float w = __int_as_float(ed.y);
        float2 lo = __half22float2(*(__half2*)&rr.x);
        float2 hi = __half22float2(*(__half2*)&rr.y);
        s0.x = fmaf(w, lo.x, s0.x); s0.y = fmaf(w, lo.y, s0.y);
        s0.z = fmaf(w, hi.x, s0.z); s0.w = fmaf(w, hi.y, s0.w);
    }

    float4 nsum;
    nsum.x = (s0.x + s1.x) + (s2.x + s3.x);
    nsum.y = (s0.y + s1.y) + (s2.y + s3.y);
    nsum.z = (s0.z + s1.z) + (s2.z + s3.z);
    nsum.w = (s0.w + s1.w) + (s2.w + s3.w);

    float4 bv = *((const float4*)bias + lane);
    float dii = di * di;
    float4 r;
    r.x = fmaxf(di * nsum.x + dii * selfLo.x + bv.x, 0.f);
    r.y = fmaxf(di * nsum.y + dii * selfLo.y + bv.y, 0.f);
    r.z = fmaxf(di * nsum.z + dii * selfHi.x + bv.z, 0.f);
    r.w = fmaxf(di * nsum.w + dii * selfHi.y + bv.w, 0.f);
    return r;
}

// agg -> fp16 output (feeds next GEMM)
__global__ void __launch_bounds__(256)
k_gcn_agg_h(const float* __restrict__ bias, __half* __restrict__ out) {
    int warp = (blockIdx.x * blockDim.x + threadIdx.x) >> 5;
    int lane = threadIdx.x & 31;
    if (warp >= NN) return;
    float4 r = agg_node(warp, lane, bias);
    __half2 h01 = __floats2half2_rn(r.x, r.y);
    __half2 h23 = __floats2half2_rn(r.z, r.w);
    uint2 o;
    o.x = *(unsigned*)&h01;
    o.y = *(unsigned*)&h23;
    *((uint2*)out + (size_t)warp * 32 + lane) = o;
}

// agg + head (x@W_lin + b_lin, log_softmax) fused
__global__ void __launch_bounds__(256)
k_agg_head(const float* __restrict__ bias, const float* __restrict__ Wl,
           const float* __restrict__ bl, float* __restrict__ out) {
    int warp = (blockIdx.x * blockDim.x + threadIdx.x) >> 5;
    int lane = threadIdx.x & 31;
    if (warp >= NN) return;
    float4 x = agg_node(warp, lane, bias);

    int c0 = lane * 4;
    float4 w01 = *(const float4*)(Wl + c0 * 2);      // rows c0, c0+1
    float4 w23 = *(const float4*)(Wl + c0 * 2 + 4);  // rows c0+2, c0+3
    float a0 = x.x * w01.x + x.y * w01.z + x.z * w23.x + x.w * w23.z;
    float a1 = x.x * w01.y + x.y * w01.w + x.z * w23.y + x.w * w23.w;
    #pragma unroll
    for (int o = 16; o > 0; o >>= 1) {
        a0 += __shfl_down_sync(0xffffffffu, a0, o);
        a1 += __shfl_down_sync(0xffffffffu, a1, o);
    }
    if (lane == 0) {
        float z0 = a0 + bl[0];
        float z1 = a1 + bl[1];
        float m  = fmaxf(z0, z1);
        float lse = m + logf(expf(z0 - m) + expf(z1 - m));
        out[(size_t)warp * 2 + 0] = z0 - lse;
        out[(size_t)warp * 2 + 1] = z1 - lse;
    }
}

// -----------------------------------------------------------------------------
extern "C" void kernel_launch(void* const* d_in, const int* in_sizes, int n_in,
                              void* d_out, int out_size) {
    const float* high  = (const float*)d_in[0];
    const float* low   = (const float*)d_in[1];
    const int*   eidx  = (const int*)d_in[2];
    const float* W_emb = (const float*)d_in[3];
    const float* b_emb = (const float*)d_in[4];
    const float* W1    = (const float*)d_in[5];
    const float* b1    = (const float*)d_in[6];
    const float* W2    = (const float*)d_in[7];
    const float* b2    = (const float*)d_in[8];
    const float* W_lin = (const float*)d_in[9];
    const float* b_lin = (const float*)d_in[10];
    float* out = (float*)d_out;

    const int* src = eidx;        // edge_index[0]
    const int* dst = eidx + EE;   // edge_index[1]

    int*    countsP; cudaGetSymbolAddress((void**)&countsP, g_counts);
    __half* embH;    cudaGetSymbolAddress((void**)&embH,    g_embH);
    __half* xlH;     cudaGetSymbolAddress((void**)&xlH,     g_xl);
    __half* x1H;     cudaGetSymbolAddress((void**)&x1H,     g_x1H);
    __half* wT;      cudaGetSymbolAddress((void**)&wT,      g_wT);

    const int T = 256;
    dim3 gE((EE + T - 1) / T);
    dim3 gWarpN((NN * 32 + T - 1) / T);
    dim3 gGemm((NN + 127) / 128);

    cudaMemsetAsync(countsP, 0, NN * sizeof(int));

    // 1-2: weight transposes needed by the first two GEMMs
    k_wT<<<(LOW * 128 + 255) / 256, 256>>>(W_emb, wT + WEMBT_OFF, LOW);          // 1
    k_wT<<<(512 * 128 + 255) / 256, 256>>>(W1, wT + W1T_OFF, 512);               // 2

    // 3: embedding: embH = relu(low @ W_emb + b_emb)  (fp16)
    k_mma<<<gGemm, 256>>>(low, LOW, (const __half*)nullptr, 0,                   // 3
                          wT + WEMBT_OFF, embH, NN, b_emb, 1);

    // 4: layer 1 (fused K=512): xl = [high | embH] @ W1 -> fp16   [ncu slot]
    k_mma<<<gGemm, 256>>>(high, HIGH, embH, EMB,                                 // 4
                          wT + W1T_OFF, xlH, NN, nullptr, 0);

    // CSR chain (independent of GEMMs; after, to keep layer-1 at slot 4)
    k_count<<<gE, T>>>(dst);                                                     // 5
    k_scan1<<<NB_SCAN, SCAN_B>>>();                                              // 6
    k_wT<<<(HID * 128 + 255) / 256, 256>>>(W2, wT + W2T_OFF, HID);               // 7
    k_scan2<<<1, 128>>>();                                                       // 8
    k_scan3<<<NB_SCAN, SCAN_B>>>();                                              // 9
    k_scatter<<<gE, T>>>(src, dst);                                              // 10

    // x1 = relu(agg(xl) + b1) -> fp16
    k_gcn_agg_h<<<gWarpN, T>>>(b1, x1H);                                         // 11

    // layer 2: xl = x1 @ W2 -> fp16
    k_mma<<<gGemm, 256>>>((const float*)nullptr, 0, x1H, HID,                    // 12
                          wT + W2T_OFF, xlH, NN, nullptr, 0);

    // agg2 + head + log_softmax (fused)
    k_agg_head<<<gWarpN, T>>>(b2, W_lin, b_lin, out);                            // 13
}

// round 15
// speedup vs baseline: 1.0464x; 1.0160x over previous
#include <cuda_runtime.h>
#include <cuda_fp16.h>
#include <math.h>

// Problem constants (fixed shapes per reference)
#define NN   100000
#define EE   3200000
#define HIGH 384
#define LOW  64
#define EMB  128
#define HID  128

#define SCAN_B 1024
#define NB_SCAN ((NN + SCAN_B - 1) / SCAN_B)   // 98

// ---------------- scratch (device globals; no allocation allowed) -------------
__device__ __align__(16) int   g_counts[NN];
__device__ __align__(16) int   g_rowptr[NN + 1];
__device__ __align__(16) int   g_cursor[NN];
__device__ __align__(16) int   g_blockSums[128];
__device__ __align__(16) int   g_blockOff[128];
__device__ __align__(16) float g_dis[NN];
__device__ __align__(16) int2  g_edge[EE];                   // (src, w bits)
__device__ __align__(16) __half g_embH[(size_t)NN * 128];    // fp16 embedding
__device__ __align__(16) __half g_xl[(size_t)NN * 128];      // fp16 pre-agg features
__device__ __align__(16) __half g_x1H[(size_t)NN * 128];     // fp16 layer-1 output
// fp16 n-major transposed weights: W1T[128][512], W2T[128][128], WembT[128][64]
__device__ __align__(16) __half g_wT[128 * 512 + 128 * 128 + 128 * 64];
#define W1T_OFF   0
#define W2T_OFF   (128 * 512)
#define WEMBT_OFF (128 * 512 + 128 * 128)

// ---------------- weight transpose+convert: W[K][128] -> WT[128][K] fp16 ------
__global__ void k_wT(const float* __restrict__ W, __half* __restrict__ WT, int K) {
    int idx = blockIdx.x * 256 + threadIdx.x;
    if (idx < K * 128) {
        int k = idx >> 7;
        int n = idx & 127;
        WT[n * K + k] = __float2half_rn(W[k * 128 + n]);
    }
}

// ---------------- degree count ----------------
__global__ void k_count(const int* __restrict__ dst) {
    int e = blockIdx.x * blockDim.x + threadIdx.x;
    if (e < EE) atomicAdd(&g_counts[dst[e]], 1);
}

// ---------------- exclusive scan of counts -> rowptr (+dis) ----------------
__global__ void k_scan1() {
    __shared__ int s[SCAN_B];
    int tid = threadIdx.x;
    int idx = blockIdx.x * SCAN_B + tid;
    int v = (idx < NN) ? g_counts[idx] : 0;
    if (idx < NN) g_dis[idx] = rsqrtf((float)v + 1.0f);
    s[tid] = v;
    __syncthreads();
    for (int off = 1; off < SCAN_B; off <<= 1) {
        int t = (tid >= off) ? s[tid - off] : 0;
        __syncthreads();
        s[tid] += t;
        __syncthreads();
    }
    if (idx < NN) g_rowptr[idx] = s[tid] - v;      // partial exclusive
    if (tid == SCAN_B - 1) g_blockSums[blockIdx.x] = s[tid];
}

__global__ void k_scan2() {
    __shared__ int s[128];
    int tid = threadIdx.x;
    int v = (tid < NB_SCAN) ? g_blockSums[tid] : 0;
    s[tid] = v;
    __syncthreads();
    for (int off = 1; off < 128; off <<= 1) {
        int t = (tid >= off) ? s[tid - off] : 0;
        __syncthreads();
        s[tid] += t;
        __syncthreads();
    }
    if (tid < NB_SCAN) g_blockOff[tid] = s[tid] - v;
    if (tid == 127) g_rowptr[NN] = s[127];         // == EE
}

__global__ void k_scan3() {
    int tid = threadIdx.x;
    int idx = blockIdx.x * SCAN_B + tid;
    if (idx < NN) {
        int r = g_rowptr[idx] + g_blockOff[blockIdx.x];
        g_rowptr[idx] = r;
        g_cursor[idx] = r;
    }
}

// ---------------- scatter edges into CSR (by dst) ----------------
__global__ void k_scatter(const int* __restrict__ src, const int* __restrict__ dst) {
    int e = blockIdx.x * blockDim.x + threadIdx.x;
    if (e < EE) {
        int d = dst[e];
        int s = src[e];
        int p = atomicAdd(&g_cursor[d], 1);
        g_edge[p] = make_int2(s, __float_as_int(g_dis[s]));
    }
}

// ---------------- cp.async helpers ----------------
__device__ __forceinline__ void cp16(void* smem, const void* gmem) {
    unsigned sa = (unsigned)__cvta_generic_to_shared(smem);
    asm volatile("cp.async.cg.shared.global [%0], [%1], 16;" :: "r"(sa), "l"(gmem));
}
__device__ __forceinline__ void cp_commit() {
    asm volatile("cp.async.commit_group;");
}
__device__ __forceinline__ void cp_wait0() {
    asm volatile("cp.async.wait_group 0;" ::: "memory");
}

// ---------------- ldmatrix helper ----------------
__device__ __forceinline__ void ldsm_x4(unsigned& r0, unsigned& r1,
                                        unsigned& r2, unsigned& r3, unsigned addr) {
    asm volatile("ldmatrix.sync.aligned.m8n8.x4.shared.b16 {%0,%1,%2,%3}, [%4];"
        : "=r"(r0), "=r"(r1), "=r"(r2), "=r"(r3) : "r"(addr));
}

// ---------------- fp16 tensor-core GEMM, async double-buffered ----------------
// C_h[M,128] = [Af | Ah] @ W  (+bias, +relu), output fp16.
// Af: fp32 A part (row stride Ka); Ah: fp16 A part (row stride Kh).
// WT: fp16 n-major weights [128][Ka+Kh].
// BM=128, BN=128, BK=32; 256 threads = 8 warps as 2(m) x 4(n); warp tile 64x32.
// Fragments via ldmatrix.x4 (bank-conflict-free on 80B row stride).

__device__ __forceinline__ void mma_f16(float* d, const unsigned* a, const unsigned* b) {
    asm volatile(
        "mma.sync.aligned.m16n8k16.row.col.f32.f16.f16.f32 "
        "{%0,%1,%2,%3}, {%4,%5,%6,%7}, {%8,%9}, {%0,%1,%2,%3};"
        : "+f"(d[0]), "+f"(d[1]), "+f"(d[2]), "+f"(d[3])
        : "r"(a[0]), "r"(a[1]), "r"(a[2]), "r"(a[3]), "r"(b[0]), "r"(b[1]));
}

#define APAD 40   // halves per SMEM row (32 data + 8 pad); 80 bytes

__global__ void __launch_bounds__(256, 2)
k_mma(const float* __restrict__ Af, int Ka,
      const __half* __restrict__ Ah, int Kh,
      const __half* __restrict__ WT, __half* __restrict__ C, int M,
      const float* __restrict__ bias, int doRelu) {
    __shared__ __half As[2][128][APAD];
    __shared__ __half Ws[2][128][APAD];

    int tid  = threadIdx.x;
    int row0 = blockIdx.x * 128;
    int warpId = tid >> 5;
    int lane   = tid & 31;
    int g   = lane >> 2;       // groupID (0..7)
    int tig = lane & 3;        // thread-in-group (0..3)
    int wr = warpId >> 2;      // 0..1  -> m offset wr*64
    int wc = warpId & 3;       // 0..3  -> n offset wc*32
    int m0 = wr * 64;
    int n0 = wc * 32;
    int K  = Ka + Kh;
    int nk = K >> 5;           // k-chunks of 32
    int nka = Ka >> 5;         // fp32 chunks

    // ldmatrix per-lane address offsets
    int lrow = lane & 7;
    int lsel = lane >> 3;                 // 0..3
    int a_row_off = (lsel & 1) * 8 + lrow; // A: matrices 0/1 = row 0/8, 2/3 = k+8
    int a_k_off   = (lsel >> 1) * 8;       // halves
    int b_row_off = (lsel >> 1) * 8 + lrow;// B: matrices 0/1 = k 0/8, 2/3 = n+8
    int b_k_off   = (lsel & 1) * 8;

    float acc[4][4][4];        // [mf][nf][c0..c3]
    #pragma unroll
    for (int i = 0; i < 4; i++)
        #pragma unroll
        for (int j = 0; j < 4; j++)
            #pragma unroll
            for (int c = 0; c < 4; c++) acc[i][j][c] = 0.0f;

    // fp32 A prefetch registers (4 float4 per thread)
    float4 rA[4];

    // ---- issue tile kc into buffer b / regs ----
    auto issue = [&](int kc, int b) {
        int k0 = kc << 5;
        if (kc < nka) {
            // fp32 A -> regs (convert at STS)
            #pragma unroll
            for (int i = 0; i < 4; i++) {
                int l   = tid + i * 256;
                int row = l >> 3;
                int c4  = (l & 7) * 4;
                int grow = row0 + row;
                float4 v = make_float4(0.f, 0.f, 0.f, 0.f);
                if (grow < M) v = *(const float4*)(Af + (size_t)grow * Ka + k0 + c4);
                rA[i] = v;
            }
        } else {
            // fp16 A -> cp.async
            int kh0 = k0 - Ka;
            #pragma unroll
            for (int i = 0; i < 2; i++) {
                int q   = tid + i * 256;
                int row = q >> 2;
                int c8  = (q & 3) * 8;
                int gr  = row0 + row; if (gr > M - 1) gr = M - 1;
                cp16(&As[b][row][c8], Ah + (size_t)gr * Kh + kh0 + c8);
            }
        }
        // W -> cp.async (WT row stride = K halves)
        #pragma unroll
        for (int i = 0; i < 2; i++) {
            int q  = tid + i * 256;
            int n  = q >> 2;
            int c8 = (q & 3) * 8;
            cp16(&Ws[b][n][c8], WT + (size_t)n * K + k0 + c8);
        }
        cp_commit();
    };

    issue(0, 0);

    for (int kc = 0; kc < nk; kc++) {
        int kb = kc & 1;
        if (kc < nka) {
            // STS prefetched fp32 A (convert now)
            #pragma unroll
            for (int i = 0; i < 4; i++) {
                int l   = tid + i * 256;
                int row = l >> 3;
                int c4  = (l & 7) * 4;
                *(__half2*)&As[kb][row][c4 + 0] = __floats2half2_rn(rA[i].x, rA[i].y);
                *(__half2*)&As[kb][row][c4 + 2] = __floats2half2_rn(rA[i].z, rA[i].w);
            }
        }
        cp_wait0();
        __syncthreads();

        if (kc + 1 < nk) issue(kc + 1, kb ^ 1);

        unsigned aBase = (unsigned)__cvta_generic_to_shared(&As[kb][0][0]);
        unsigned wBase = (unsigned)__cvta_generic_to_shared(&Ws[kb][0][0]);

        #pragma unroll
        for (int ks = 0; ks < 2; ks++) {   // two k16 steps
            int kh = ks * 16;
            unsigned af[4][4];
            #pragma unroll
            for (int mf = 0; mf < 4; mf++) {
                unsigned ad = aBase +
                    ((unsigned)(m0 + mf * 16 + a_row_off) * APAD + kh + a_k_off) * 2u;
                ldsm_x4(af[mf][0], af[mf][1], af[mf][2], af[mf][3], ad);
            }
            unsigned bf[4][2];
            #pragma unroll
            for (int nfp = 0; nfp < 2; nfp++) {
                unsigned bd = wBase +
                    ((unsigned)(n0 + nfp * 16 + b_row_off) * APAD + kh + b_k_off) * 2u;
                ldsm_x4(bf[2 * nfp][0], bf[2 * nfp][1],
                        bf[2 * nfp + 1][0], bf[2 * nfp + 1][1], bd);
            }
            #pragma unroll
            for (int mf = 0; mf < 4; mf++)
                #pragma unroll
                for (int nf = 0; nf < 4; nf++)
                    mma_f16(acc[mf][nf], af[mf], bf[nf]);
        }
        __syncthreads();
    }

    // --- epilogue (fp16 out) ---
    #pragma unroll
    for (int mf = 0; mf < 4; mf++) {
        int ra = row0 + m0 + mf * 16 + g;     // row for c0,c1
        int rb = ra + 8;                      // row for c2,c3
        #pragma unroll
        for (int nf = 0; nf < 4; nf++) {
            int col = n0 + nf * 8 + 2 * tig;
            float b0 = bias ? bias[col]     : 0.0f;
            float b1 = bias ? bias[col + 1] : 0.0f;
            #pragma unroll
            for (int h = 0; h < 2; h++) {
                int r = h ? rb : ra;
                if (r >= M) continue;
                float2 o = make_float2(acc[mf][nf][2 * h]     + b0,
                                       acc[mf][nf][2 * h + 1] + b1);
                if (doRelu) { o.x = fmaxf(o.x, 0.f); o.y = fmaxf(o.y, 0.f); }
                *(__half2*)(C + (size_t)r * 128 + col) = __float22half2_rn(o);
            }
        }
    }
}

// ---------------- GCN aggregation core (fp16 gathers), one warp per node ------
// 4 independent gather streams per warp, plain fp32 fmaf accumulate.
__device__ __forceinline__ float4 agg_node(int i, int lane, const float* bias) {
    float di = g_dis[i];
    const uint2* xb = (const uint2*)g_xl;     // index: node*32 + lane
    uint2 sr = __ldg(xb + (size_t)i * 32 + lane);
    float2 selfLo = __half22float2(*(__half2*)&sr.x);
    float2 selfHi = __half22float2(*(__half2*)&sr.y);

    int beg = g_rowptr[i];
    int end = g_rowptr[i + 1];

    float4 s0 = make_float4(0.f, 0.f, 0.f, 0.f);
    float4 s1 = make_float4(0.f, 0.f, 0.f, 0.f);
    float4 s2 = make_float4(0.f, 0.f, 0.f, 0.f);
    float4 s3 = make_float4(0.f, 0.f, 0.f, 0.f);

    int e = beg;
    for (; e + 4 <= end; e += 4) {
        int2 e0 = g_edge[e + 0], e1 = g_edge[e + 1];
        int2 e2 = g_edge[e + 2], e3 = g_edge[e + 3];
        uint2 r0 = __ldg(xb + (size_t)e0.x * 32 + lane);
        uint2 r1 = __ldg(xb + (size_t)e1.x * 32 + lane);
        uint2 r2 = __ldg(xb + (size_t)e2.x * 32 + lane);
        uint2 r3 = __ldg(xb + (size_t)e3.x * 32 + lane);
        float w0 = __int_as_float(e0.y), w1 = __int_as_float(e1.y);
        float w2 = __int_as_float(e2.y), w3 = __int_as_float(e3.y);
        {
            float2 lo = __half22float2(*(__half2*)&r0.x);
            float2 hi = __half22float2(*(__half2*)&r0.y);
            s0.x = fmaf(w0, lo.x, s0.x); s0.y = fmaf(w0, lo.y, s0.y);
            s0.z = fmaf(w0, hi.x, s0.z); s0.w = fmaf(w0, hi.y, s0.w);
        }
        {
            float2 lo = __half22float2(*(__half2*)&r1.x);
            float2 hi = __half22float2(*(__half2*)&r1.y);
            s1.x = fmaf(w1, lo.x, s1.x); s1.y = fmaf(w1, lo.y, s1.y);
            s1.z = fmaf(w1, hi.x, s1.z); s1.w = fmaf(w1, hi.y, s1.w);
        }
        {
            float2 lo = __half22float2(*(__half2*)&r2.x);
            float2 hi = __half22float2(*(__half2*)&r2.y);
            s2.x = fmaf(w2, lo.x, s2.x); s2.y = fmaf(w2, lo.y, s2.y);
            s2.z = fmaf(w2, hi.x, s2.z); s2.w = fmaf(w2, hi.y, s2.w);
        }
        {
            float2 lo = __half22float2(*(__half2*)&r3.x);
            float2 hi = __half22float2(*(__half2*)&r3.y);
            s3.x = fmaf(w3, lo.x, s3.x); s3.y = fmaf(w3, lo.y, s3.y);
            s3.z = fmaf(w3, hi.x, s3.z); s3.w = fmaf(w3, hi.y, s3.w);
        }
    }
    for (; e < end; e++) {
        int2 ed = g_edge[e];
        uint2 rr = __ldg(xb + (size_t)ed.x * 32 + lane);
        float w = __int_as_float(ed.y);
        float2 lo = __half22float2(*(__half2*)&rr.x);
        float2 hi = __half22float2(*(__half2*)&rr.y);
        s0.x = fmaf(w, lo.x, s0.x); s0.y = fmaf(w, lo.y, s0.y);
        s0.z = fmaf(w, hi.x, s0.z); s0.w = fmaf(w, hi.y, s0.w);
    }

    float4 nsum;
    nsum.x = (s0.x + s1.x) + (s2.x + s3.x);
    nsum.y = (s0.y + s1.y) + (s2.y + s3.y);
    nsum.z = (s0.z + s1.z) + (s2.z + s3.z);
    nsum.w = (s0.w + s1.w) + (s2.w + s3.w);

    float4 bv = *((const float4*)bias + lane);
    float dii = di * di;
    float4 r;
    r.x = fmaxf(di * nsum.x + dii * selfLo.x + bv.x, 0.f);
    r.y = fmaxf(di * nsum.y + dii * selfLo.y + bv.y, 0.f);
    r.z = fmaxf(di * nsum.z + dii * selfHi.x + bv.z, 0.f);
    r.w = fmaxf(di * nsum.w + dii * selfHi.y + bv.w, 0.f);
    return r;
}

// agg -> fp16 output (feeds next GEMM)
__global__ void __launch_bounds__(256)
k_gcn_agg_h(const float* __restrict__ bias, __half* __restrict__ out) {
    int warp = (blockIdx.x * blockDim.x + threadIdx.x) >> 5;
    int lane = threadIdx.x & 31;
    if (warp >= NN) return;
    float4 r = agg_node(warp, lane, bias);
    __half2 h01 = __floats2half2_rn(r.x, r.y);
    __half2 h23 = __floats2half2_rn(r.z, r.w);
    uint2 o;
    o.x = *(unsigned*)&h01;
    o.y = *(unsigned*)&h23;
    *((uint2*)out + (size_t)warp * 32 + lane) = o;
}

// agg + head (x@W_lin + b_lin, log_softmax) fused
__global__ void __launch_bounds__(256)
k_agg_head(const float* __restrict__ bias, const float* __restrict__ Wl,
           const float* __restrict__ bl, float* __restrict__ out) {
    int warp = (blockIdx.x * blockDim.x + threadIdx.x) >> 5;
    int lane = threadIdx.x & 31;
    if (warp >= NN) return;
    float4 x = agg_node(warp, lane, bias);

    int c0 = lane * 4;
    float4 w01 = *(const float4*)(Wl + c0 * 2);      // rows c0, c0+1
    float4 w23 = *(const float4*)(Wl + c0 * 2 + 4);  // rows c0+2, c0+3
    float a0 = x.x * w01.x + x.y * w01.z + x.z * w23.x + x.w * w23.z;
    float a1 = x.x * w01.y + x.y * w01.w + x.z * w23.y + x.w * w23.w;
    #pragma unroll
    for (int o = 16; o > 0; o >>= 1) {
        a0 += __shfl_down_sync(0xffffffffu, a0, o);
        a1 += __shfl_down_sync(0xffffffffu, a1, o);
    }
    if (lane == 0) {
        float z0 = a0 + bl[0];
        float z1 = a1 + bl[1];
        float m  = fmaxf(z0, z1);
        float lse = m + logf(expf(z0 - m) + expf(z1 - m));
        out[(size_t)warp * 2 + 0] = z0 - lse;
        out[(size_t)warp * 2 + 1] = z1 - lse;
    }
}

// -----------------------------------------------------------------------------
extern "C" void kernel_launch(void* const* d_in, const int* in_sizes, int n_in,
                              void* d_out, int out_size) {
    const float* high  = (const float*)d_in[0];
    const float* low   = (const float*)d_in[1];
    const int*   eidx  = (const int*)d_in[2];
    const float* W_emb = (const float*)d_in[3];
    const float* b_emb = (const float*)d_in[4];
    const float* W1    = (const float*)d_in[5];
    const float* b1    = (const float*)d_in[6];
    const float* W2    = (const float*)d_in[7];
    const float* b2    = (const float*)d_in[8];
    const float* W_lin = (const float*)d_in[9];
    const float* b_lin = (const float*)d_in[10];
    float* out = (float*)d_out;

    const int* src = eidx;        // edge_index[0]
    const int* dst = eidx + EE;   // edge_index[1]

    int*    countsP; cudaGetSymbolAddress((void**)&countsP, g_counts);
    __half* embH;    cudaGetSymbolAddress((void**)&embH,    g_embH);
    __half* xlH;     cudaGetSymbolAddress((void**)&xlH,     g_xl);
    __half* x1H;     cudaGetSymbolAddress((void**)&x1H,     g_x1H);
    __half* wT;      cudaGetSymbolAddress((void**)&wT,      g_wT);

    const int T = 256;
    dim3 gE((EE + T - 1) / T);
    dim3 gWarpN((NN * 32 + T - 1) / T);
    dim3 gGemm((NN + 127) / 128);

    // Fresh side stream + fork/join events each call (no static state, no
    // device allocation; host handles are intentionally not destroyed because
    // the side stream is part of the capture graph).
    cudaStream_t s2;
    cudaEvent_t evFork, evJoin;
    cudaStreamCreateWithFlags(&s2, cudaStreamNonBlocking);
    cudaEventCreateWithFlags(&evFork, cudaEventDisableTiming);
    cudaEventCreateWithFlags(&evJoin, cudaEventDisableTiming);

    // ---- fork: CSR build on s2, GEMM chain on the launch stream ----
    cudaEventRecord(evFork, 0);
    cudaStreamWaitEvent(s2, evFork, 0);

    // CSR chain (s2)
    cudaMemsetAsync(countsP, 0, NN * sizeof(int), s2);
    k_count<<<gE, T, 0, s2>>>(dst);
    k_scan1<<<NB_SCAN, SCAN_B, 0, s2>>>();
    k_scan2<<<1, 128, 0, s2>>>();
    k_scan3<<<NB_SCAN, SCAN_B, 0, s2>>>();
    k_scatter<<<gE, T, 0, s2>>>(src, dst);
    cudaEventRecord(evJoin, s2);

    // GEMM chain (launch stream), concurrent with CSR build
    k_wT<<<(LOW * 128 + 255) / 256, 256>>>(W_emb, wT + WEMBT_OFF, LOW);
    k_wT<<<(512 * 128 + 255) / 256, 256>>>(W1, wT + W1T_OFF, 512);
    k_wT<<<(HID * 128 + 255) / 256, 256>>>(W2, wT + W2T_OFF, HID);
    // embedding: embH = relu(low @ W_emb + b_emb)  (fp16)
    k_mma<<<gGemm, 256>>>(low, LOW, (const __half*)nullptr, 0,
                          wT + WEMBT_OFF, embH, NN, b_emb, 1);
    // layer 1 (fused K=512): xl = [high | embH] @ W1 -> fp16
    k_mma<<<gGemm, 256>>>(high, HIGH, embH, EMB,
                          wT + W1T_OFF, xlH, NN, nullptr, 0);

    // ---- join ----
    cudaStreamWaitEvent(0, evJoin, 0);

    // x1 = relu(agg(xl) + b1) -> fp16
    k_gcn_agg_h<<<gWarpN, T>>>(b1, x1H);

    // layer 2: xl = x1 @ W2 -> fp16
    k_mma<<<gGemm, 256>>>((const float*)nullptr, 0, x1H, HID,
                          wT + W2T_OFF, xlH, NN, nullptr, 0);

    // agg2 + head + log_softmax (fused)
    k_agg_head<<<gWarpN, T>>>(b2, W_lin, b_lin, out);
}